// round 4
// baseline (speedup 1.0000x reference)
#include <cuda_runtime.h>
#include <math.h>

#define ZNUM  64
#define CELLS 64
#define C1    64   // BASE_C
#define C2    32   // Z_C
#define BMAX  64

// hidden activations h = silu(conv1(log1p(tof_map)))  [b][ch][cell]
__device__ float g_h[BMAX * C1 * CELLS];

// ---------- robust input decoding helpers ----------

// mask layout: 0 = int32, 1 = float32, 2 = byte/bool
__device__ __forceinline__ int detect_mask_layout(const void* p) {
    const unsigned* w = (const unsigned*)p;
    bool all_int = true, all_float = true;
    for (int i = 0; i < 256; ++i) {   // 1KB scan: safe for byte layout (>=4096B)
        unsigned v = w[i];
        if (v != 0u && v != 1u) all_int = false;
        if (v != 0u && v != 0x3F800000u) all_float = false;
    }
    if (all_int) return 0;
    if (all_float) return 1;
    return 2;
}

__device__ __forceinline__ int read_dim(const void* p) {
    int   iv = ((const int*)p)[0];
    float fv = ((const float*)p)[0];
    bool int_ok = (iv >= 8 && iv <= 1000000);
    if (!int_ok && fv >= 8.f && fv <= 1.0e6f && floorf(fv) == fv) return (int)fv;
    return iv;
}

__device__ __forceinline__ int read_mask(const void* p, int idx, int layout) {
    if (layout == 0) return ((const int*)p)[idx] != 0;
    if (layout == 1) return ((const float*)p)[idx] != 0.0f;
    return ((const unsigned char*)p)[idx] != 0;
}

// ---------- Kernel A: pooled tof map + log1p + 1x1 conv + SiLU ----------

__global__ __launch_bounds__(256)
void kA(const float* __restrict__ hist,     // [B,Z,2]
        const void*  __restrict__ maskp,    // [B,Z]  (layout auto-detected)
        const int*   __restrict__ fr,       // [B,Z,4]
        const void*  __restrict__ Hp, const void* __restrict__ Wp,
        const float* __restrict__ w1,       // [C1,2]
        const float* __restrict__ b1)       // [C1]
{
    const int b   = blockIdx.x;
    const int tid = threadIdx.x;
    const int H = read_dim(Hp);
    const int W = read_dim(Wp);
    const int mlayout = detect_mask_layout(maskp);

    __shared__ int   s_sy[ZNUM], s_sx[ZNUM], s_ey[ZNUM], s_ex[ZNUM];
    __shared__ int   s_mk[ZNUM];
    __shared__ float s_mv[ZNUM], s_vv[ZNUM];
    __shared__ float s_x[CELLS][2];   // log1p'ed (mean, var) per pooled cell

    if (tid < ZNUM) {
        const int z = tid;
        const int* bx = fr + ((long)b * ZNUM + z) * 4;
        s_sy[z] = max(bx[0], 0);
        s_sx[z] = max(bx[1], 0);
        s_ey[z] = min(bx[2], H);
        s_ex[z] = min(bx[3], W);
        s_mk[z] = read_mask(maskp, b * ZNUM + z, mlayout);
        s_mv[z] = hist[((long)b * ZNUM + z) * 2 + 0];
        s_vv[z] = hist[((long)b * ZNUM + z) * 2 + 1];
    }
    __syncthreads();

    const int bh = H / 8, bw = W / 8;
    const float inv_area = 1.0f / (float)(bh * bw);

    if (tid < CELLS) {
        const int r = tid >> 3, c = tid & 7;
        const int cy0 = r * bh, cy1 = cy0 + bh;
        const int cx0 = c * bw, cx1 = cx0 + bw;

        float sm = 0.f, sv = 0.f;
        bool fb = false;
        // last-write-wins: highest z that overlaps decides
        for (int z = ZNUM - 1; z >= 0; --z) {
            if (!s_mk[z]) continue;
            int iy0 = max(s_sy[z], cy0), iy1 = min(s_ey[z], cy1);
            int ix0 = max(s_sx[z], cx0), ix1 = min(s_ex[z], cx1);
            if (iy0 >= iy1 || ix0 >= ix1) continue;
            if (iy0 == cy0 && iy1 == cy1 && ix0 == cx0 && ix1 == cx1) {
                sm = s_mv[z] * (float)(bh * bw);
                sv = s_vv[z] * (float)(bh * bw);
            } else {
                fb = true;   // partial overlap -> exact per-pixel fallback
            }
            break;
        }
        if (fb) {
            sm = 0.f; sv = 0.f;
            for (int y = cy0; y < cy1; ++y)
                for (int x = cx0; x < cx1; ++x)
                    for (int z = ZNUM - 1; z >= 0; --z) {
                        if (!s_mk[z]) continue;
                        if (y >= s_sy[z] && y < s_ey[z] &&
                            x >= s_sx[z] && x < s_ex[z]) {
                            sm += s_mv[z]; sv += s_vv[z];
                            break;
                        }
                    }
        }
        float tm = sm * inv_area, tv = sv * inv_area;
        s_x[tid][0] = log1pf(fmaxf(tm, 0.f));
        s_x[tid][1] = log1pf(fmaxf(tv, 0.f));
    }
    __syncthreads();

    // 1x1 conv (2 -> C1) + SiLU, write ch-major for conv2
    for (int i = tid; i < C1 * CELLS; i += blockDim.x) {
        const int ch = i >> 6, cell = i & 63;
        float v = w1[ch * 2 + 0] * s_x[cell][0]
                + w1[ch * 2 + 1] * s_x[cell][1] + b1[ch];
        float h = v / (1.f + expf(-v));
        g_h[((long)b * C1 + ch) * CELLS + cell] = h;
    }
}

// ---------- Kernel B: 3x3 conv (C1 -> C2), pad 1, 8x8 map ----------
// grid = (4, B): 4 oc-groups of 8.  block = 128: (ic-half 2) x (oc_local 8) x (row 8)

__global__ __launch_bounds__(128)
void kB(const float* __restrict__ w2,   // [C2,C1,3,3]
        const float* __restrict__ b2,   // [C2]
        float* __restrict__ out)        // [B,C2,8,8]
{
    const int ocg = blockIdx.x;
    const int b   = blockIdx.y;
    const int tid = threadIdx.x;
    const int half = tid >> 6;       // ic split: 0 -> ic[0,32), 1 -> ic[32,64)
    const int l    = tid & 63;
    const int ol   = l >> 3;         // oc within group
    const int row  = l & 7;
    const int oc   = ocg * 8 + ol;

    __shared__ __align__(16) float hs[C1 * 64];       // 16 KB activations
    __shared__ __align__(16) float ws[8 * C1 * 12];   // 24 KB weights (9 + pad 3)

    const float* hb = g_h + (long)b * C1 * CELLS;
    for (int i = tid * 4; i < C1 * 64; i += 128 * 4)
        *(float4*)(hs + i) = *(const float4*)(hb + i);

    for (int i = tid; i < 8 * C1 * 9; i += 128) {
        int k = i % 9; int ic = (i / 9) & 63; int o = i / (9 * C1);
        ws[(o * C1 + ic) * 12 + k] = w2[((oc - ol + o) * C1 + ic) * 9 + k];
    }
    for (int i = tid; i < 8 * C1; i += 128) {
        ws[i * 12 + 9] = 0.f; ws[i * 12 + 10] = 0.f; ws[i * 12 + 11] = 0.f;
    }
    __syncthreads();

    float acc[8];
#pragma unroll
    for (int x = 0; x < 8; ++x) acc[x] = 0.f;

    const int ic0 = half * 32;
#pragma unroll 4
    for (int ic = ic0; ic < ic0 + 32; ++ic) {
        const float* hrow = hs + ic * 64;
        float rm[10], r0[10], rp[10];
        rm[0] = rm[9] = r0[0] = r0[9] = rp[0] = rp[9] = 0.f;

        if (row > 0) {
            float4 a = *(const float4*)(hrow + (row - 1) * 8);
            float4 d = *(const float4*)(hrow + (row - 1) * 8 + 4);
            rm[1]=a.x; rm[2]=a.y; rm[3]=a.z; rm[4]=a.w;
            rm[5]=d.x; rm[6]=d.y; rm[7]=d.z; rm[8]=d.w;
        } else {
#pragma unroll
            for (int x = 1; x < 9; ++x) rm[x] = 0.f;
        }
        {
            float4 a = *(const float4*)(hrow + row * 8);
            float4 d = *(const float4*)(hrow + row * 8 + 4);
            r0[1]=a.x; r0[2]=a.y; r0[3]=a.z; r0[4]=a.w;
            r0[5]=d.x; r0[6]=d.y; r0[7]=d.z; r0[8]=d.w;
        }
        if (row < 7) {
            float4 a = *(const float4*)(hrow + (row + 1) * 8);
            float4 d = *(const float4*)(hrow + (row + 1) * 8 + 4);
            rp[1]=a.x; rp[2]=a.y; rp[3]=a.z; rp[4]=a.w;
            rp[5]=d.x; rp[6]=d.y; rp[7]=d.z; rp[8]=d.w;
        } else {
#pragma unroll
            for (int x = 1; x < 9; ++x) rp[x] = 0.f;
        }

        const float* wp = ws + (ol * C1 + ic) * 12;
        const float w00=wp[0], w01=wp[1], w02=wp[2];
        const float w10=wp[3], w11=wp[4], w12=wp[5];
        const float w20=wp[6], w21=wp[7], w22=wp[8];
#pragma unroll
        for (int x = 0; x < 8; ++x) {
            acc[x] += w00*rm[x] + w01*rm[x+1] + w02*rm[x+2]
                    + w10*r0[x] + w11*r0[x+1] + w12*r0[x+2]
                    + w20*rp[x] + w21*rp[x+1] + w22*rp[x+2];
        }
    }

    __syncthreads();           // hs free for reduction now
    if (half == 1) {
        float* red = hs + l * 8;
#pragma unroll
        for (int x = 0; x < 8; ++x) red[x] = acc[x];
    }
    __syncthreads();
    if (half == 0) {
        const float* red = hs + l * 8;
        const float bias = b2[oc];
        float* op = out + (((long)b * C2 + oc) * 8 + row) * 8;
#pragma unroll
        for (int x = 0; x < 8; ++x) op[x] = acc[x] + red[x] + bias;
    }
}

// ---------- launch ----------

extern "C" void kernel_launch(void* const* d_in, const int* in_sizes, int n_in,
                              void* d_out, int out_size)
{
    // input order: hist_BZ2, mask_BZ, fr_BZ4, H, W, w1, b1, w2, b2
    const float* hist  = (const float*)d_in[0];
    const void*  maskp = d_in[1];
    const int*   fr    = (const int*)d_in[2];
    const void*  Hp    = d_in[3];
    const void*  Wp    = d_in[4];
    const float* w1    = (const float*)d_in[5];
    const float* b1    = (const float*)d_in[6];
    const float* w2    = (const float*)d_in[7];
    const float* b2    = (const float*)d_in[8];
    float* out = (float*)d_out;

    int B = in_sizes[1] / ZNUM;      // mask has B*Z elements
    if (B < 1) B = 1;
    if (B > BMAX) B = BMAX;

    kA<<<B, 256>>>(hist, maskp, fr, Hp, Wp, w1, b1);
    kB<<<dim3(4, B), 128>>>(w2, b2, out);
}

// round 5
// speedup vs baseline: 1.2662x; 1.2662x over previous
#include <cuda_runtime.h>
#include <math.h>

#define ZNUM  64
#define CELLS 64
#define C1    64   // BASE_C
#define C2    32   // Z_C
#define BMAX  64

// ---------- robust input decoding helpers ----------

__device__ __forceinline__ int read_dim(const void* p) {
    int   iv = ((const int*)p)[0];
    float fv = ((const float*)p)[0];
    bool int_ok = (iv >= 8 && iv <= 1000000);
    if (!int_ok && fv >= 8.f && fv <= 1.0e6f && floorf(fv) == fv) return (int)fv;
    return iv;
}

__device__ __forceinline__ int read_mask(const void* p, int idx, int layout) {
    if (layout == 0) return ((const int*)p)[idx] != 0;
    if (layout == 1) return ((const float*)p)[idx] != 0.0f;
    return ((const unsigned char*)p)[idx] != 0;
}

// ---------- fused kernel ----------
// grid = (8 ic-groups? no: 8 oc-split? -> (icsplit folded in-block))
// grid = (8, B): blockIdx.x = ocg (4 oc each). block = 256 threads:
//   warp w (=tid>>5) handles ic range [w*8, w*8+8)
//   within warp: ol = (tid&31)>>3 (oc 0..3), row = tid&7
// Prologue (pooling + 1x1 conv + SiLU) recomputed per block (cheap).

__global__ __launch_bounds__(256)
void kFused(const float* __restrict__ hist,     // [B,Z,2]
            const void*  __restrict__ maskp,    // [B,Z]
            const int*   __restrict__ fr,       // [B,Z,4]
            const void*  __restrict__ Hp, const void* __restrict__ Wp,
            const float* __restrict__ w1,       // [C1,2]
            const float* __restrict__ b1,       // [C1]
            const float* __restrict__ w2,       // [C2,C1,3,3]
            const float* __restrict__ b2,       // [C2]
            float* __restrict__ out,            // [B,C2,8,8]
            int nwords)                         // bounded mask-scan length
{
    const int ocg = blockIdx.x;       // 0..7 -> oc base ocg*4
    const int b   = blockIdx.y;
    const int tid = threadIdx.x;

    __shared__ int   s_sy[ZNUM], s_sx[ZNUM], s_ey[ZNUM], s_ex[ZNUM];
    __shared__ float s_mv[ZNUM], s_vv[ZNUM];
    __shared__ int   s_mk[ZNUM];
    __shared__ float s_x[CELLS][2];
    __shared__ __align__(16) float hs[C1 * 64];          // 16 KB activations
    __shared__ __align__(16) float ws[4 * C1 * 12];      // 12 KB weights (pad 12)
    __shared__ __align__(16) float redbuf[8 * 256];      // 8 KB ic-split partials

    const int H = read_dim(Hp);
    const int W = read_dim(Wp);

    // ---- mask layout detection (cooperative, bounded) ----
    int p_int = 1, p_float = 1;
    if (tid < 64) {
        const unsigned* mw = (const unsigned*)maskp;
        for (int i = 0; i < 4; ++i) {
            int idx = tid * 4 + i;
            if (idx < nwords) {
                unsigned v = mw[idx];
                if (v != 0u && v != 1u) p_int = 0;
                if (v != 0u && v != 0x3F800000u) p_float = 0;
            }
        }
    }
    // also stage zone data before the barrier
    if (tid < ZNUM) {
        const int z = tid;
        const int* bx = fr + ((long)b * ZNUM + z) * 4;
        s_sy[z] = max(bx[0], 0);
        s_sx[z] = max(bx[1], 0);
        s_ey[z] = min(bx[2], H);
        s_ex[z] = min(bx[3], W);
        s_mv[z] = hist[((long)b * ZNUM + z) * 2 + 0];
        s_vv[z] = hist[((long)b * ZNUM + z) * 2 + 1];
    }
    int all_int   = __syncthreads_and(p_int);     // full barrier + reduce
    int all_float = __syncthreads_and(p_float);
    const int mlayout = all_int ? 0 : (all_float ? 1 : 2);

    if (tid < ZNUM)
        s_mk[tid] = read_mask(maskp, b * ZNUM + tid, mlayout);
    __syncthreads();

    // ---- pooling (lazy exact scatter+area-pool) + log1p ----
    const int bh = H / 8, bw = W / 8;
    const float inv_area = 1.0f / (float)(bh * bw);

    if (tid < CELLS) {
        const int r = tid >> 3, c = tid & 7;
        const int cy0 = r * bh, cy1 = cy0 + bh;
        const int cx0 = c * bw, cx1 = cx0 + bw;

        float sm = 0.f, sv = 0.f;
        bool fb = false;
        for (int z = ZNUM - 1; z >= 0; --z) {          // last-write-wins
            if (!s_mk[z]) continue;
            int iy0 = max(s_sy[z], cy0), iy1 = min(s_ey[z], cy1);
            int ix0 = max(s_sx[z], cx0), ix1 = min(s_ex[z], cx1);
            if (iy0 >= iy1 || ix0 >= ix1) continue;
            if (iy0 == cy0 && iy1 == cy1 && ix0 == cx0 && ix1 == cx1) {
                sm = s_mv[z] * (float)(bh * bw);
                sv = s_vv[z] * (float)(bh * bw);
            } else {
                fb = true;  // partial cover -> exact per-pixel fallback
            }
            break;
        }
        if (fb) {
            sm = 0.f; sv = 0.f;
            for (int y = cy0; y < cy1; ++y)
                for (int x = cx0; x < cx1; ++x)
                    for (int z = ZNUM - 1; z >= 0; --z) {
                        if (!s_mk[z]) continue;
                        if (y >= s_sy[z] && y < s_ey[z] &&
                            x >= s_sx[z] && x < s_ex[z]) {
                            sm += s_mv[z]; sv += s_vv[z];
                            break;
                        }
                    }
        }
        float tm = sm * inv_area, tv = sv * inv_area;
        s_x[tid][0] = log1pf(fmaxf(tm, 0.f));
        s_x[tid][1] = log1pf(fmaxf(tv, 0.f));
    }

    // ---- stage conv2 weights for this block's 4 oc (independent of s_x) ----
    {
        const int oc0 = ocg * 4;
        for (int i = tid; i < 4 * C1 * 9; i += 256) {
            int k = i % 9; int ic = (i / 9) & 63; int o = i / (9 * C1);
            ws[(o * C1 + ic) * 12 + k] = w2[((oc0 + o) * C1 + ic) * 9 + k];
        }
    }
    __syncthreads();

    // ---- 1x1 conv (2 -> C1) + SiLU into smem ----
    for (int i = tid; i < C1 * CELLS; i += 256) {
        const int ch = i >> 6, cell = i & 63;
        float v = fmaf(w1[ch * 2 + 0], s_x[cell][0],
                  fmaf(w1[ch * 2 + 1], s_x[cell][1], b1[ch]));
        hs[i] = v * (1.0f / (1.0f + __expf(-v)));
    }
    __syncthreads();

    // ---- 3x3 conv mainloop: warp = ic-group of 8 ----
    const int icg = tid >> 5;          // 0..7
    const int l   = tid & 31;
    const int ol  = l >> 3;            // 0..3  (oc within block)
    const int row = l & 7;

    float acc[8];
#pragma unroll
    for (int x = 0; x < 8; ++x) acc[x] = 0.f;

    const int ic0 = icg * 8;
#pragma unroll 2
    for (int ii = 0; ii < 8; ++ii) {
        const int ic = ic0 + ii;
        const float* hrow = hs + ic * 64;

        float rm[10], r0[10], rp[10];
        rm[0] = rm[9] = r0[0] = r0[9] = rp[0] = rp[9] = 0.f;

        if (row > 0) {
            float4 a = *(const float4*)(hrow + (row - 1) * 8);
            float4 d = *(const float4*)(hrow + (row - 1) * 8 + 4);
            rm[1]=a.x; rm[2]=a.y; rm[3]=a.z; rm[4]=a.w;
            rm[5]=d.x; rm[6]=d.y; rm[7]=d.z; rm[8]=d.w;
        } else {
#pragma unroll
            for (int x = 1; x < 9; ++x) rm[x] = 0.f;
        }
        {
            float4 a = *(const float4*)(hrow + row * 8);
            float4 d = *(const float4*)(hrow + row * 8 + 4);
            r0[1]=a.x; r0[2]=a.y; r0[3]=a.z; r0[4]=a.w;
            r0[5]=d.x; r0[6]=d.y; r0[7]=d.z; r0[8]=d.w;
        }
        if (row < 7) {
            float4 a = *(const float4*)(hrow + (row + 1) * 8);
            float4 d = *(const float4*)(hrow + (row + 1) * 8 + 4);
            rp[1]=a.x; rp[2]=a.y; rp[3]=a.z; rp[4]=a.w;
            rp[5]=d.x; rp[6]=d.y; rp[7]=d.z; rp[8]=d.w;
        } else {
#pragma unroll
            for (int x = 1; x < 9; ++x) rp[x] = 0.f;
        }

        const float* wp = ws + (ol * C1 + ic) * 12;     // 48B-aligned
        const float4 wa = *(const float4*)(wp);         // w00 w01 w02 w10
        const float4 wb = *(const float4*)(wp + 4);     // w11 w12 w20 w21
        const float4 wc = *(const float4*)(wp + 8);     // w22 (pad x3)
        const float w00=wa.x, w01=wa.y, w02=wa.z, w10=wa.w;
        const float w11=wb.x, w12=wb.y, w20=wb.z, w21=wb.w;
        const float w22=wc.x;

#pragma unroll
        for (int x = 0; x < 8; ++x) {
            float s = acc[x];
            s = fmaf(w00, rm[x],   s); s = fmaf(w01, rm[x+1], s); s = fmaf(w02, rm[x+2], s);
            s = fmaf(w10, r0[x],   s); s = fmaf(w11, r0[x+1], s); s = fmaf(w12, r0[x+2], s);
            s = fmaf(w20, rp[x],   s); s = fmaf(w21, rp[x+1], s); s = fmaf(w22, rp[x+2], s);
            acc[x] = s;
        }
    }

    // ---- 8-way ic-split reduction via smem ----
    {
        float* rb = redbuf + icg * 256 + l * 8;
#pragma unroll
        for (int x = 0; x < 8; ++x) rb[x] = acc[x];
    }
    __syncthreads();

    // thread t owns output element t of the block's 4x64 tile
    {
        const int oc_l = tid >> 6;            // 0..3
        const int pix  = tid & 63;
        float s = b2[ocg * 4 + oc_l];
#pragma unroll
        for (int g = 0; g < 8; ++g) s += redbuf[g * 256 + tid];
        out[(((long)b * C2 + ocg * 4 + oc_l) * 64) + pix] = s;
    }
}

// ---------- launch ----------

extern "C" void kernel_launch(void* const* d_in, const int* in_sizes, int n_in,
                              void* d_out, int out_size)
{
    // input order: hist_BZ2, mask_BZ, fr_BZ4, H, W, w1, b1, w2, b2
    const float* hist  = (const float*)d_in[0];
    const void*  maskp = d_in[1];
    const int*   fr    = (const int*)d_in[2];
    const void*  Hp    = d_in[3];
    const void*  Wp    = d_in[4];
    const float* w1    = (const float*)d_in[5];
    const float* b1    = (const float*)d_in[6];
    const float* w2    = (const float*)d_in[7];
    const float* b2    = (const float*)d_in[8];
    float* out = (float*)d_out;

    int B = in_sizes[1] / ZNUM;      // mask has B*Z elements
    if (B < 1) B = 1;
    if (B > BMAX) B = BMAX;

    int nwords = in_sizes[1] / 4;    // worst case: byte layout -> B*Z/4 words
    if (nwords > 256) nwords = 256;
    if (nwords < 1) nwords = 1;

    kFused<<<dim3(8, B), 256>>>(hist, maskp, fr, Hp, Wp,
                                w1, b1, w2, b2, out, nwords);
}